// round 13
// baseline (speedup 1.0000x reference)
#include <cuda_runtime.h>
#include <cuda_bf16.h>
#include <cstddef>

// NetAE batch-1 forward: HBM-bound GEMV chain (~596MB fp32 weights/call).
// Round 13 (base = round 12, 118.8us):
//  - SELECTIVE early PDL trigger: A, DE, F trigger right after their own
//    grid-dependency sync, so their successors (B, F, G — all with register
//    weight prefetch and small grids) stream weights DURING the producer.
//    B/C/G/out keep end-trigger (successors have no pre-sync work / huge
//    grids -> r9 showed blanket early triggering loses to SM squatting).
//  - DE's D-dot reduction: warp shuffle + one __syncthreads (was 3-sync tree).
// Everything else identical to round 12.

#define D_H    2048
#define D_A    256
#define N_EXP  16
#define D_OUT  512

__device__ float g_pA[128 * 2048];
__device__ float g_pB[128 * 2048];
__device__ float g_pC[16 * 32 * 2048];
__device__ float g_pDs[16 * 64];         // per-block k.q scalar partials
__device__ float g_pE[512 * 2048];       // UNSCALED V partials
__device__ float g_pF[128 * 2048];
__device__ float g_pG[256 * 512];

__device__ __forceinline__ float4 f4add(float4 a, float4 b) {
    return make_float4(a.x + b.x, a.y + b.y, a.z + b.z, a.w + b.w);
}

// ---------------------------------------------------------------------------
// Shared prologue: build sx[RPS] = x-slice [i0, i0+RPS).
//   MODE 0: sx[r] = xsrc[i0+r]
//   MODE 1: sx[r] = [relu](biasx[bb*NPREV+i0+r] + sum_{s<SPREV} xsrc[(bb*SPREV+s)*NPREV+i0+r])
// ---------------------------------------------------------------------------
template<int BLK, int RPS, int MODE, int SPREV, int NPREV, bool RELU_X, bool PREV_PER_B>
__device__ __forceinline__
void stage_x(float* sx, const float* __restrict__ xsrc,
             const float* __restrict__ biasx, int i0, int b)
{
    const int tid = threadIdx.x;
    if constexpr (MODE == 0) {
        for (int r = tid; r < RPS; r += BLK) sx[r] = xsrc[i0 + r];
        __syncthreads();
    } else {
        constexpr int NQ = RPS / 4;
        constexpr int CH = BLK / NQ;
        __shared__ float4 sxp4[BLK];
        const int q = tid % NQ;
        const int c = tid / NQ;
        const int bb = PREV_PER_B ? b : 0;
        const float4* p = reinterpret_cast<const float4*>(
            xsrc + ((size_t)bb * SPREV) * NPREV + i0);
        float4 v = make_float4(0.f, 0.f, 0.f, 0.f);
        #pragma unroll
        for (int s = c; s < SPREV; s += CH)
            v = f4add(v, p[(size_t)s * (NPREV / 4) + q]);
        sxp4[tid] = v;
        __syncthreads();
        if (tid < NQ) {
            float4 v2 = reinterpret_cast<const float4*>(
                            biasx + (size_t)bb * NPREV + i0)[tid];
            #pragma unroll
            for (int cc = 0; cc < CH; cc++) v2 = f4add(v2, sxp4[tid + cc * NQ]);
            if constexpr (RELU_X) {
                v2.x = fmaxf(v2.x, 0.f); v2.y = fmaxf(v2.y, 0.f);
                v2.z = fmaxf(v2.z, 0.f); v2.w = fmaxf(v2.w, 0.f);
            }
            reinterpret_cast<float4*>(sx)[tid] = v2;
        }
        __syncthreads();
    }
}

// Generic split-K GEMV stage. PF = rows prefetched into regs before the wait.
// EARLY = fire the PDL trigger right after the grid-dependency sync.
template<int BLK, int RPS, int N, int GRP, int MODE, int SPREV, int NPREV,
         bool RELU_X, bool PREV_PER_B, int PF, bool EARLY>
__global__ __launch_bounds__(BLK)
void gemv_k(const float* __restrict__ W,
            const float* __restrict__ xsrc,
            const float* __restrict__ biasx,
            float* __restrict__ partOut)
{
    __shared__ float sx[RPS];
    const int tid   = threadIdx.x;
    const int slice = blockIdx.y;
    const int b     = blockIdx.z;
    const int S     = gridDim.y;
    const int i0    = slice * RPS;
    const int K     = S * RPS;

    constexpr int CT  = BLK / GRP;
    constexpr int RPG = RPS / GRP;
    const int g  = tid / CT;
    const int j  = (blockIdx.x * CT + (tid % CT)) * 4;
    const int r0 = g * RPG;
    const float* Wp = W + (size_t)b * K * N + (size_t)(i0 + r0) * N + j;

    float4 wreg[PF > 0 ? PF : 1];
    #pragma unroll
    for (int rr = 0; rr < PF; rr++)
        wreg[rr] = *reinterpret_cast<const float4*>(Wp + (size_t)rr * N);

    cudaGridDependencySynchronize();
    if constexpr (EARLY) cudaTriggerProgrammaticLaunchCompletion();

    stage_x<BLK, RPS, MODE, SPREV, NPREV, RELU_X, PREV_PER_B>(sx, xsrc, biasx, i0, b);

    float4 acc = make_float4(0.f, 0.f, 0.f, 0.f);
    #pragma unroll
    for (int rr = 0; rr < PF; rr++) {
        const float xi = sx[r0 + rr];
        acc.x += xi * wreg[rr].x; acc.y += xi * wreg[rr].y;
        acc.z += xi * wreg[rr].z; acc.w += xi * wreg[rr].w;
    }
    #pragma unroll 16
    for (int rr = PF; rr < RPG; rr++) {
        const float4 w = *reinterpret_cast<const float4*>(Wp + (size_t)rr * N);
        const float xi = sx[r0 + rr];
        acc.x += xi * w.x; acc.y += xi * w.y;
        acc.z += xi * w.z; acc.w += xi * w.w;
    }
    *reinterpret_cast<float4*>(
        partOut + ((size_t)((b * S + slice) * GRP + g)) * N + j) = acc;
    if constexpr (!EARLY) cudaTriggerProgrammaticLaunchCompletion();
}

// ---------------------------------------------------------------------------
// Merged D+E stage, uniform 1024 blocks. grid = (2, 32, 16).
// D-tile dots its k-partial with q in-kernel -> one scalar per block (pDs).
// EARLY trigger: F launches at DE start and prefetches W_t during DE.
// ---------------------------------------------------------------------------
__global__ __launch_bounds__(256)
void gemv_DE(const float* __restrict__ Wv, const float* __restrict__ Wk,
             const float* __restrict__ pC, const float* __restrict__ b_exp,
             const float* __restrict__ W_q, const float* __restrict__ b_q,
             const int* __restrict__ task_id,
             float* __restrict__ pE, float* __restrict__ pDs)
{
    __shared__ float sx[64];
    __shared__ float redD[8];
    const int tid   = threadIdx.x;
    const int xp    = blockIdx.x;
    const int slice = blockIdx.y;
    const int b     = blockIdx.z;
    const int i0    = slice * 64;

    cudaGridDependencySynchronize();
    cudaTriggerProgrammaticLaunchCompletion();   // EARLY: F prefetches now
    stage_x<256, 64, 1, 32, 2048, true, true>(sx, pC, b_exp, i0, b);

    // ---- E tile ----
    {
        const int j = (xp * 256 + tid) * 4;
        const float* Wp = Wv + (size_t)b * 2048 * 2048 + (size_t)i0 * 2048 + j;
        float4 acc = make_float4(0.f, 0.f, 0.f, 0.f);
        #pragma unroll 16
        for (int rr = 0; rr < 64; rr++) {
            const float4 w = *reinterpret_cast<const float4*>(Wp + (size_t)rr * 2048);
            const float xi = sx[rr];
            acc.x += xi * w.x; acc.y += xi * w.y;
            acc.z += xi * w.z; acc.w += xi * w.w;
        }
        *reinterpret_cast<float4*>(pE + ((size_t)(b * 32 + slice)) * 2048 + j) = acc;
    }
    // ---- D tile -> scalar k.q partial (warp-shuffle reduce) ----
    {
        const int g  = tid / 32;
        const int jd = xp * 128 + (tid % 32) * 4;
        const int r0 = g * 8;
        const float* Wp = Wk + (size_t)b * 2048 * 256 + (size_t)(i0 + r0) * 256 + jd;
        float4 acc = make_float4(0.f, 0.f, 0.f, 0.f);
        #pragma unroll
        for (int rr = 0; rr < 8; rr++) {
            const float4 w = *reinterpret_cast<const float4*>(Wp + (size_t)rr * 256);
            const float xi = sx[r0 + rr];
            acc.x += xi * w.x; acc.y += xi * w.y;
            acc.z += xi * w.z; acc.w += xi * w.w;
        }
        const int t = *task_id;
        const float4 wq = *reinterpret_cast<const float4*>(
            W_q + ((size_t)t * 10 + t) * D_A + jd);
        const float4 bq = *reinterpret_cast<const float4*>(b_q + t * D_A + jd);
        float s = acc.x * (wq.x + bq.x) + acc.y * (wq.y + bq.y)
                + acc.z * (wq.z + bq.z) + acc.w * (wq.w + bq.w);
        #pragma unroll
        for (int off = 16; off; off >>= 1) s += __shfl_xor_sync(0xFFFFFFFFu, s, off);
        if ((tid & 31) == 0) redD[g] = s;
        __syncthreads();
        if (tid == 0) {
            float v = redD[0] + redD[1] + redD[2] + redD[3]
                    + redD[4] + redD[5] + redD[6] + redD[7];
            pDs[b * 64 + slice * 2 + xp] = v;
        }
    }
}

// ---------------------------------------------------------------------------
// F stage: prologue reconstructs ekq[16] from pDs + b_k.q, then MODE-2
// staging (ekq-weighted reduce of pE + ekq.b_v), then GEMV vs W_t with full
// register prefetch (streams during DE thanks to DE's early trigger).
// EARLY trigger: G prefetches W_l during F.
// ---------------------------------------------------------------------------
__global__ __launch_bounds__(256)
void gemv_F(const float* __restrict__ W_t, const float* __restrict__ pE,
            const float* __restrict__ pDs, const float* __restrict__ b_k,
            const float* __restrict__ W_q, const float* __restrict__ b_q,
            const float* __restrict__ b_v, const int* __restrict__ task_id,
            float* __restrict__ pF)
{
    __shared__ float sekq[16];
    __shared__ float tmp[256];
    __shared__ float4 sxp4[256];
    __shared__ float sx[16];
    const int tid = threadIdx.x;
    const int slice = blockIdx.y;
    const int i0 = slice * 16;
    const int j  = (blockIdx.x * 256 + tid) * 4;
    const float* Wp = W_t + (size_t)i0 * 2048 + j;

    float4 wreg[16];
    #pragma unroll
    for (int rr = 0; rr < 16; rr++)
        wreg[rr] = *reinterpret_cast<const float4*>(Wp + (size_t)rr * 2048);

    cudaGridDependencySynchronize();
    cudaTriggerProgrammaticLaunchCompletion();   // EARLY: G prefetches now

    // ekq[n] = sum_{i<64} pDs[n*64+i] + dot(b_k[n], q)
    {
        const int t = *task_id;
        const int n = tid >> 4;
        const int l = tid & 15;
        float s = 0.f;
        #pragma unroll
        for (int k = 0; k < 16; k++) {
            const int a = l * 16 + k;
            const float qv = W_q[((size_t)t * 10 + t) * D_A + a] + b_q[t * D_A + a];
            s += b_k[n * D_A + a] * qv;
        }
        tmp[tid] = s;
        __syncthreads();
        if (tid < 16) {
            float v = 0.f;
            #pragma unroll
            for (int l2 = 0; l2 < 16; l2++) v += tmp[tid * 16 + l2];
            #pragma unroll
            for (int i = 0; i < 64; i++) v += pDs[tid * 64 + i];
            sekq[tid] = v;
        }
        __syncthreads();
    }

    // MODE-2 staging: sx[16] = ekq-weighted reduce of 512 pE rows + ekq.b_v
    {
        const int q4 = tid % 4;
        const int c  = tid / 4;
        const float4* p = reinterpret_cast<const float4*>(pE + i0);
        float4 v = make_float4(0.f, 0.f, 0.f, 0.f);
        #pragma unroll
        for (int s = c; s < 512; s += 64) {
            float4 w = p[(size_t)s * 512 + q4];
            const float sc = sekq[s >> 5];
            v.x += sc * w.x; v.y += sc * w.y;
            v.z += sc * w.z; v.w += sc * w.w;
        }
        sxp4[tid] = v;
        __syncthreads();
        if (tid < 4) {
            float4 v2 = make_float4(0.f, 0.f, 0.f, 0.f);
            #pragma unroll
            for (int cc = 0; cc < 64; cc++) v2 = f4add(v2, sxp4[tid + cc * 4]);
            #pragma unroll
            for (int n = 0; n < N_EXP; n++) {
                const float4 bq = reinterpret_cast<const float4*>(
                    b_v + (size_t)n * 2048 + i0)[tid];
                const float e = sekq[n];
                v2.x += e * bq.x; v2.y += e * bq.y;
                v2.z += e * bq.z; v2.w += e * bq.w;
            }
            reinterpret_cast<float4*>(sx)[tid] = v2;
        }
        __syncthreads();
    }

    float4 acc = make_float4(0.f, 0.f, 0.f, 0.f);
    #pragma unroll
    for (int rr = 0; rr < 16; rr++) {
        const float xi = sx[rr];
        acc.x += xi * wreg[rr].x; acc.y += xi * wreg[rr].y;
        acc.z += xi * wreg[rr].z; acc.w += xi * wreg[rr].w;
    }
    *reinterpret_cast<float4*>(pF + ((size_t)slice) * 2048 + j) = acc;
}

// out[j] = b_l[j] + reduce_{s<256} pG[s*512 + j];  8 blocks x 256 thr.
__global__ __launch_bounds__(256)
void fin_out(const float* __restrict__ part,
             const float* __restrict__ b_l,
             float* __restrict__ out)
{
    __shared__ float4 red4[256];
    const int ql = threadIdx.x % 16;
    const int c  = threadIdx.x / 16;
    const int jq = blockIdx.x * 16 + ql;
    cudaGridDependencySynchronize();
    const float4* p = reinterpret_cast<const float4*>(part);
    float4 acc = make_float4(0.f, 0.f, 0.f, 0.f);
    #pragma unroll 8
    for (int s = c; s < 256; s += 16) acc = f4add(acc, p[(size_t)s * 128 + jq]);
    red4[threadIdx.x] = acc;
    __syncthreads();
    #pragma unroll
    for (int off = 8; off >= 1; off >>= 1) {
        if (c < off) red4[threadIdx.x] = f4add(red4[threadIdx.x],
                                               red4[threadIdx.x + off * 16]);
        __syncthreads();
    }
    if (c == 0) {
        float4 v = f4add(red4[ql], reinterpret_cast<const float4*>(b_l)[jq]);
        reinterpret_cast<float4*>(out)[jq] = v;
    }
    cudaTriggerProgrammaticLaunchCompletion();
}

// ---------------------------------------------------------------------------
template<typename K, typename... A>
static inline void launch_pdl(K kern, dim3 g, dim3 b, A... args)
{
    cudaLaunchConfig_t cfg = {};
    cfg.gridDim = g;
    cfg.blockDim = b;
    cfg.stream = 0;
    cudaLaunchAttribute at[1];
    at[0].id = cudaLaunchAttributeProgrammaticStreamSerialization;
    at[0].val.programmaticStreamSerializationAllowed = 1;
    cfg.attrs = at;
    cfg.numAttrs = 1;
    cudaLaunchKernelEx(&cfg, kern, args...);
}

extern "C" void kernel_launch(void* const* d_in, const int* in_sizes, int n_in,
                              void* d_out, int out_size)
{
    const float* x     = (const float*)d_in[0];
    const float* W1    = (const float*)d_in[1];
    const float* b1    = (const float*)d_in[2];
    const float* W2    = (const float*)d_in[3];
    const float* b2    = (const float*)d_in[4];
    const float* W_exp = (const float*)d_in[5];
    const float* b_exp = (const float*)d_in[6];
    const float* W_v   = (const float*)d_in[7];
    const float* b_v   = (const float*)d_in[8];
    const float* W_k   = (const float*)d_in[9];
    const float* b_k   = (const float*)d_in[10];
    const float* W_q   = (const float*)d_in[11];
    const float* b_q   = (const float*)d_in[12];
    const float* W_t   = (const float*)d_in[13];
    const float* b_t   = (const float*)d_in[14];
    const float* W_l   = (const float*)d_in[15];
    const float* b_l   = (const float*)d_in[16];
    const int*   tid   = (const int*)d_in[17];
    float* out = (float*)d_out;

    float *pA, *pB, *pC, *pDs, *pE, *pF, *pG;
    cudaGetSymbolAddress((void**)&pA, g_pA);
    cudaGetSymbolAddress((void**)&pB, g_pB);
    cudaGetSymbolAddress((void**)&pC, g_pC);
    cudaGetSymbolAddress((void**)&pDs, g_pDs);
    cudaGetSymbolAddress((void**)&pE, g_pE);
    cudaGetSymbolAddress((void**)&pF, g_pF);
    cudaGetSymbolAddress((void**)&pG, g_pG);

    // A: pA = splitK(x @ W1)       16MB, EARLY trigger (B prefetches W2 during A)
    launch_pdl(gemv_k<256, 16, 2048, 1, 0, 0, 1, false, false, 16, true>,
               dim3(2, 128, 1), dim3(256), W1, x, (const float*)nullptr, pA);
    // B: h1 fused; pB = splitK(h1 @ W2)   16MB, end trigger (C has no prefetch)
    launch_pdl(gemv_k<256, 16, 2048, 1, 1, 128, 2048, true, false, 16, false>,
               dim3(2, 128, 1), dim3(256), W2, pA, b1, pB);
    // C: h2 fused; pC[n] = splitK(h2 @ W_exp[n])   256MB, end trigger
    launch_pdl(gemv_k<256, 64, 2048, 1, 1, 128, 2048, true, false, 0, false>,
               dim3(2, 32, 16), dim3(256), W_exp, pB, b2, pC);
    // D+E merged + in-kernel k.q dot      288MB, EARLY (F streams W_t during DE)
    launch_pdl(gemv_DE, dim3(2, 32, 16), dim3(256),
               W_v, W_k, pC, b_exp, W_q, b_q, tid, pE, pDs);
    // F: ekq in-prologue; res fused; pF = splitK(res @ W_t)  16MB, EARLY
    launch_pdl(gemv_F, dim3(2, 128, 1), dim3(256),
               W_t, pE, pDs, b_k, W_q, b_q, b_v, tid, pF);
    // G: t fused; pG = splitK(t @ W_l)    4MB, end trigger
    launch_pdl(gemv_k<256, 16, 512, 2, 1, 128, 2048, true, false, 8, false>,
               dim3(1, 128, 1), dim3(256), W_l, pF, b_t, pG);
    // out
    launch_pdl(fin_out, dim3(8), dim3(256), pG, b_l, out);
}